// round 16
// baseline (speedup 1.0000x reference)
#include <cuda_runtime.h>
#include <cstdint>

#define DM   1024
#define NH   16
#define DH   64
#define BATCH 2
#define SEQ  2048
#define MROWS (BATCH*SEQ)   // 4096

// ---------------- scratch (device globals: allocation-free) ----------------
__device__ float g_Q[(size_t)BATCH*NH*SEQ*DH];   // [B,H,N,64]
__device__ float g_K[(size_t)BATCH*NH*SEQ*DH];   // [B,H,N,64]
__device__ float g_V[(size_t)BATCH*NH*SEQ*DH];   // [B,H,N,64]
__device__ float g_O[(size_t)MROWS*DM];          // [B,N,H*64] row-major

// ---------------- helpers ----------------
__device__ __forceinline__ uint32_t f2tf(float x) {
    uint32_t u;
    asm("cvt.rna.tf32.f32 %0, %1;" : "=r"(u) : "f"(x));
    return u;
}
__device__ __forceinline__ float f2tf_f(float x) { return __uint_as_float(f2tf(x)); }

__device__ __forceinline__ void mma8(float* c,
                                     uint32_t a0, uint32_t a1, uint32_t a2, uint32_t a3,
                                     uint32_t b0, uint32_t b1) {
    asm volatile(
        "mma.sync.aligned.m16n8k8.row.col.f32.tf32.tf32.f32 "
        "{%0,%1,%2,%3},{%4,%5,%6,%7},{%8,%9},{%0,%1,%2,%3};"
        : "+f"(c[0]), "+f"(c[1]), "+f"(c[2]), "+f"(c[3])
        : "r"(a0), "r"(a1), "r"(a2), "r"(a3), "r"(b0), "r"(b1));
}

// ---------------- TF32 GEMM: C[4096,1024] = A[4096,1024] * W[1024,1024] ----------------
// MODE 0: epilogue scatters to [B,H,N,64] (selected by `which`: 0->g_Q,1->g_K,2->g_V)
// MODE 1: A is g_O, epilogue adds bias, writes row-major to Cout.
template <int MODE>
__global__ void __launch_bounds__(256) gemm_tf32(const float* __restrict__ A,
                                                 const float* __restrict__ W,
                                                 const float* __restrict__ bias,
                                                 float* __restrict__ Cout,
                                                 int which) {
    __shared__ float As[128 * 36];   // stride 36: banks 4*gid+tig -> conflict-free
    __shared__ float Bs[32 * 136];   // stride 136: banks 8*tig+gid -> conflict-free

    const int tid  = threadIdx.x;
    const int warp = tid >> 5, lane = tid & 31;
    const int gid  = lane >> 2, tig = lane & 3;
    const int wm   = (warp >> 2) * 64;   // warp m-offset (2 warps in m)
    const int wn   = (warp & 3) * 32;    // warp n-offset (4 warps in n)
    const int bm   = blockIdx.y * 128;
    const int bn   = blockIdx.x * 128;

    const float* Ap = (MODE == 0) ? A : g_O;

    float acc[4][4][4];
#pragma unroll
    for (int i = 0; i < 4; i++)
#pragma unroll
        for (int j = 0; j < 4; j++)
#pragma unroll
            for (int r = 0; r < 4; r++) acc[i][j][r] = 0.f;

    const int a_r = tid >> 3, a_c = (tid & 7) * 4;    // A tile: 128x32
    const int b_r = tid >> 5, b_c = (tid & 31) * 4;   // B tile: 32x128

    for (int kt = 0; kt < DM / 32; kt++) {
#pragma unroll
        for (int i = 0; i < 4; i++) {
            int r = a_r + i * 32;
            float4 v = *(const float4*)(Ap + (size_t)(bm + r) * DM + kt * 32 + a_c);
            As[r * 36 + a_c + 0] = f2tf_f(v.x);
            As[r * 36 + a_c + 1] = f2tf_f(v.y);
            As[r * 36 + a_c + 2] = f2tf_f(v.z);
            As[r * 36 + a_c + 3] = f2tf_f(v.w);
        }
#pragma unroll
        for (int i = 0; i < 4; i++) {
            int r = b_r + i * 8;
            float4 v = *(const float4*)(W + (size_t)(kt * 32 + r) * DM + bn + b_c);
            Bs[r * 136 + b_c + 0] = f2tf_f(v.x);
            Bs[r * 136 + b_c + 1] = f2tf_f(v.y);
            Bs[r * 136 + b_c + 2] = f2tf_f(v.z);
            Bs[r * 136 + b_c + 3] = f2tf_f(v.w);
        }
        __syncthreads();

#pragma unroll
        for (int ks = 0; ks < 4; ks++) {
            uint32_t af[4][4];
#pragma unroll
            for (int mt = 0; mt < 4; mt++) {
                int r0 = wm + mt * 16 + gid;
                af[mt][0] = __float_as_uint(As[r0 * 36 + ks * 8 + tig]);
                af[mt][1] = __float_as_uint(As[(r0 + 8) * 36 + ks * 8 + tig]);
                af[mt][2] = __float_as_uint(As[r0 * 36 + ks * 8 + tig + 4]);
                af[mt][3] = __float_as_uint(As[(r0 + 8) * 36 + ks * 8 + tig + 4]);
            }
            uint32_t bf[4][2];
#pragma unroll
            for (int nt = 0; nt < 4; nt++) {
                int cc = wn + nt * 8 + gid;
                bf[nt][0] = __float_as_uint(Bs[(ks * 8 + tig) * 136 + cc]);
                bf[nt][1] = __float_as_uint(Bs[(ks * 8 + tig + 4) * 136 + cc]);
            }
#pragma unroll
            for (int mt = 0; mt < 4; mt++)
#pragma unroll
                for (int nt = 0; nt < 4; nt++)
                    mma8(acc[mt][nt], af[mt][0], af[mt][1], af[mt][2], af[mt][3],
                         bf[nt][0], bf[nt][1]);
        }
        __syncthreads();
    }

    // -------- epilogue --------
    float* C = Cout;
    if (MODE == 0) C = (which == 0) ? g_Q : (which == 1) ? g_K : g_V;

#pragma unroll
    for (int mt = 0; mt < 4; mt++) {
#pragma unroll
        for (int nt = 0; nt < 4; nt++) {
            int row = bm + wm + mt * 16 + gid;
            int col = bn + wn + nt * 8 + 2 * tig;
            if (MODE == 0) {
                // scatter to [B,H,N,64]
                int b = row >> 11, n = row & 2047;
                int h = col >> 6, d = col & 63;
                float2* p0 = (float2*)(C + ((((size_t)b * NH + h) * SEQ + n) * DH + d));
                *p0 = make_float2(acc[mt][nt][0], acc[mt][nt][1]);
                float2* p1 = (float2*)(C + ((((size_t)b * NH + h) * SEQ + (n + 8)) * DH + d));
                *p1 = make_float2(acc[mt][nt][2], acc[mt][nt][3]);
            } else {
                float2 bv = *(const float2*)(bias + col);
                *(float2*)(C + (size_t)row * DM + col) =
                    make_float2(acc[mt][nt][0] + bv.x, acc[mt][nt][1] + bv.y);
                *(float2*)(C + (size_t)(row + 8) * DM + col) =
                    make_float2(acc[mt][nt][2] + bv.x, acc[mt][nt][3] + bv.y);
            }
        }
    }
}

// ---------------- flash attention (TF32 mma, online softmax) ----------------
// grid: (SEQ/128, B*NH); block: 256 threads = 8 warps x 16 query rows
__global__ void __launch_bounds__(256) flash_attn() {
    __shared__ float Ks[64 * 68];   // stride 68: S b-frag banks 4*gid+tig
    __shared__ float Vs[64 * 72];   // stride 72: PV b-frag banks 8*tig+gid

    const int tid  = threadIdx.x;
    const int warp = tid >> 5, lane = tid & 31;
    const int gid  = lane >> 2, tig = lane & 3;
    const int qt = blockIdx.x, bh = blockIdx.y;

    const float* Qb = g_Q + (size_t)bh * SEQ * DH;
    const float* Kb = g_K + (size_t)bh * SEQ * DH;
    const float* Vb = g_V + (size_t)bh * SEQ * DH;

    const int   qr0 = qt * 128 + warp * 16;
    const float QS  = 0.125f * 1.4426950408889634f;  // scale * log2(e)

    // Q fragments: loaded once, pre-scaled + tf32-rounded
    uint32_t qf[8][4];
#pragma unroll
    for (int ks = 0; ks < 8; ks++) {
        int c = ks * 8 + tig;
        qf[ks][0] = f2tf(Qb[(size_t)(qr0 + gid) * DH + c] * QS);
        qf[ks][1] = f2tf(Qb[(size_t)(qr0 + gid + 8) * DH + c] * QS);
        qf[ks][2] = f2tf(Qb[(size_t)(qr0 + gid) * DH + c + 4] * QS);
        qf[ks][3] = f2tf(Qb[(size_t)(qr0 + gid + 8) * DH + c + 4] * QS);
    }

    float o[8][4];
#pragma unroll
    for (int nt = 0; nt < 8; nt++)
#pragma unroll
        for (int r = 0; r < 4; r++) o[nt][r] = 0.f;
    float m0 = -1e30f, m1 = -1e30f, l0 = 0.f, l1 = 0.f;

    const int tr = tid >> 4, tc = (tid & 15) * 4;   // K/V tile loading: 64 rows x 16 float4

    for (int kt = 0; kt < SEQ / 64; kt++) {
        __syncthreads();  // previous tile's smem reads done
#pragma unroll
        for (int i = 0; i < 4; i++) {
            int r = tr + i * 16;
            float4 kv = *(const float4*)(Kb + (size_t)(kt * 64 + r) * DH + tc);
            Ks[r * 68 + tc + 0] = f2tf_f(kv.x);
            Ks[r * 68 + tc + 1] = f2tf_f(kv.y);
            Ks[r * 68 + tc + 2] = f2tf_f(kv.z);
            Ks[r * 68 + tc + 3] = f2tf_f(kv.w);
            float4 vv = *(const float4*)(Vb + (size_t)(kt * 64 + r) * DH + tc);
            Vs[r * 72 + tc + 0] = f2tf_f(vv.x);
            Vs[r * 72 + tc + 1] = f2tf_f(vv.y);
            Vs[r * 72 + tc + 2] = f2tf_f(vv.z);
            Vs[r * 72 + tc + 3] = f2tf_f(vv.w);
        }
        __syncthreads();

        // ---- S = (Q*scale*log2e) K^T : [16 x 64] per warp ----
        float s[8][4];
#pragma unroll
        for (int nt = 0; nt < 8; nt++)
#pragma unroll
            for (int r = 0; r < 4; r++) s[nt][r] = 0.f;

#pragma unroll
        for (int ks = 0; ks < 8; ks++) {
#pragma unroll
            for (int nt = 0; nt < 8; nt++) {
                uint32_t b0 = __float_as_uint(Ks[(nt * 8 + gid) * 68 + ks * 8 + tig]);
                uint32_t b1 = __float_as_uint(Ks[(nt * 8 + gid) * 68 + ks * 8 + tig + 4]);
                mma8(s[nt], qf[ks][0], qf[ks][1], qf[ks][2], qf[ks][3], b0, b1);
            }
        }

        // ---- online softmax (exp2 domain) ----
        float tm0 = -1e30f, tm1 = -1e30f;
#pragma unroll
        for (int nt = 0; nt < 8; nt++) {
            tm0 = fmaxf(tm0, fmaxf(s[nt][0], s[nt][1]));
            tm1 = fmaxf(tm1, fmaxf(s[nt][2], s[nt][3]));
        }
        tm0 = fmaxf(tm0, __shfl_xor_sync(0xffffffffu, tm0, 1));
        tm0 = fmaxf(tm0, __shfl_xor_sync(0xffffffffu, tm0, 2));
        tm1 = fmaxf(tm1, __shfl_xor_sync(0xffffffffu, tm1, 1));
        tm1 = fmaxf(tm1, __shfl_xor_sync(0xffffffffu, tm1, 2));

        float mn0 = fmaxf(m0, tm0), mn1 = fmaxf(m1, tm1);
        float al0 = exp2f(m0 - mn0), al1 = exp2f(m1 - mn1);
        m0 = mn0; m1 = mn1;

        float rs0 = 0.f, rs1 = 0.f;
#pragma unroll
        for (int nt = 0; nt < 8; nt++) {
            float p0 = exp2f(s[nt][0] - m0);
            float p1 = exp2f(s[nt][1] - m0);
            float p2 = exp2f(s[nt][2] - m1);
            float p3 = exp2f(s[nt][3] - m1);
            rs0 += p0 + p1;
            rs1 += p2 + p3;
            s[nt][0] = f2tf_f(p0);
            s[nt][1] = f2tf_f(p1);
            s[nt][2] = f2tf_f(p2);
            s[nt][3] = f2tf_f(p3);
        }
        rs0 += __shfl_xor_sync(0xffffffffu, rs0, 1);
        rs0 += __shfl_xor_sync(0xffffffffu, rs0, 2);
        rs1 += __shfl_xor_sync(0xffffffffu, rs1, 1);
        rs1 += __shfl_xor_sync(0xffffffffu, rs1, 2);
        l0 = l0 * al0 + rs0;
        l1 = l1 * al1 + rs1;

#pragma unroll
        for (int nt = 0; nt < 8; nt++) {
            o[nt][0] *= al0; o[nt][1] *= al0;
            o[nt][2] *= al1; o[nt][3] *= al1;
        }

        // ---- O += P V : shuffle-reshape P (c-frag) into A-frag layout ----
#pragma unroll
        for (int ks = 0; ks < 8; ks++) {
            int srcA = (lane & ~3) | (tig >> 1);
            int srcB = srcA + 2;
            float w00 = __shfl_sync(0xffffffffu, s[ks][0], srcA);
            float w01 = __shfl_sync(0xffffffffu, s[ks][1], srcA);
            float w02 = __shfl_sync(0xffffffffu, s[ks][0], srcB);
            float w03 = __shfl_sync(0xffffffffu, s[ks][1], srcB);
            float w10 = __shfl_sync(0xffffffffu, s[ks][2], srcA);
            float w11 = __shfl_sync(0xffffffffu, s[ks][3], srcA);
            float w12 = __shfl_sync(0xffffffffu, s[ks][2], srcB);
            float w13 = __shfl_sync(0xffffffffu, s[ks][3], srcB);
            bool odd = (tig & 1);
            uint32_t pa0 = __float_as_uint(odd ? w01 : w00);
            uint32_t pa2 = __float_as_uint(odd ? w03 : w02);
            uint32_t pa1 = __float_as_uint(odd ? w11 : w10);
            uint32_t pa3 = __float_as_uint(odd ? w13 : w12);
#pragma unroll
            for (int nt = 0; nt < 8; nt++) {
                uint32_t b0 = __float_as_uint(Vs[(ks * 8 + tig) * 72 + nt * 8 + gid]);
                uint32_t b1 = __float_as_uint(Vs[(ks * 8 + tig + 4) * 72 + nt * 8 + gid]);
                mma8(o[nt], pa0, pa1, pa2, pa3, b0, b1);
            }
        }
    }

    // ---- normalize + write O to [B, N, H*64] ----
    float i0 = 1.f / l0, i1 = 1.f / l1;
    int b = bh >> 4, h = bh & 15;
    int row0 = qr0 + gid;
#pragma unroll
    for (int nt = 0; nt < 8; nt++) {
        int col = h * 64 + nt * 8 + 2 * tig;
        *(float2*)(g_O + (size_t)(b * SEQ + row0) * DM + col) =
            make_float2(o[nt][0] * i0, o[nt][1] * i0);
        *(float2*)(g_O + (size_t)(b * SEQ + row0 + 8) * DM + col) =
            make_float2(o[nt][2] * i1, o[nt][3] * i1);
    }
}

// ---------------- launch ----------------
extern "C" void kernel_launch(void* const* d_in, const int* in_sizes, int n_in,
                              void* d_out, int out_size) {
    const float* q  = (const float*)d_in[0];
    const float* k  = (const float*)d_in[1];
    const float* v  = (const float*)d_in[2];
    const float* Wq = (const float*)d_in[3];
    const float* Wk = (const float*)d_in[4];
    const float* Wv = (const float*)d_in[5];
    const float* Wo = (const float*)d_in[6];
    const float* bo = (const float*)d_in[7];
    float* out = (float*)d_out;

    dim3 g(DM / 128, MROWS / 128);  // (8, 32)
    gemm_tf32<0><<<g, 256>>>(q, Wq, nullptr, nullptr, 0);
    gemm_tf32<0><<<g, 256>>>(k, Wk, nullptr, nullptr, 1);
    gemm_tf32<0><<<g, 256>>>(v, Wv, nullptr, nullptr, 2);
    flash_attn<<<dim3(SEQ / 128, BATCH * NH), 256>>>();
    gemm_tf32<1><<<g, 256>>>(nullptr, Wo, bo, out, 3);
}

// round 17
// speedup vs baseline: 1.0034x; 1.0034x over previous
#include <cuda_runtime.h>
#include <cstdint>

#define DM   1024
#define NH   16
#define DH   64
#define BATCH 2
#define SEQ  2048
#define MROWS (BATCH*SEQ)   // 4096

// ---------------- scratch (device globals: allocation-free) ----------------
__device__ float g_Q[(size_t)BATCH*NH*SEQ*DH];   // [B,H,N,64]
__device__ float g_K[(size_t)BATCH*NH*SEQ*DH];   // [B,H,N,64]
__device__ float g_V[(size_t)BATCH*NH*SEQ*DH];   // [B,H,N,64]
__device__ float g_O[(size_t)MROWS*DM];          // [B,N,H*64] row-major

// ---------------- helpers ----------------
__device__ __forceinline__ uint32_t f2tf(float x) {
    uint32_t u;
    asm("cvt.rna.tf32.f32 %0, %1;" : "=r"(u) : "f"(x));
    return u;
}
__device__ __forceinline__ float f2tf_f(float x) { return __uint_as_float(f2tf(x)); }

__device__ __forceinline__ void mma8(float* c,
                                     uint32_t a0, uint32_t a1, uint32_t a2, uint32_t a3,
                                     uint32_t b0, uint32_t b1) {
    asm volatile(
        "mma.sync.aligned.m16n8k8.row.col.f32.tf32.tf32.f32 "
        "{%0,%1,%2,%3},{%4,%5,%6,%7},{%8,%9},{%0,%1,%2,%3};"
        : "+f"(c[0]), "+f"(c[1]), "+f"(c[2]), "+f"(c[3])
        : "r"(a0), "r"(a1), "r"(a2), "r"(a3), "r"(b0), "r"(b1));
}

// ---------------- TF32 GEMM: C[4096,1024] = A[4096,1024] * W[1024,1024] ----------------
// MODE 0: epilogue scatters to [B,H,N,64] (selected by `which`: 0->g_Q,1->g_K,2->g_V)
// MODE 1: A is g_O, epilogue adds bias, writes row-major to Cout.
template <int MODE>
__global__ void __launch_bounds__(256) gemm_tf32(const float* __restrict__ A,
                                                 const float* __restrict__ W,
                                                 const float* __restrict__ bias,
                                                 float* __restrict__ Cout,
                                                 int which) {
    __shared__ float As[128 * 36];   // stride 36: banks 4*gid+tig -> conflict-free
    __shared__ float Bs[32 * 136];   // stride 136: banks 8*tig+gid -> conflict-free

    const int tid  = threadIdx.x;
    const int warp = tid >> 5, lane = tid & 31;
    const int gid  = lane >> 2, tig = lane & 3;
    const int wm   = (warp >> 2) * 64;   // warp m-offset (2 warps in m)
    const int wn   = (warp & 3) * 32;    // warp n-offset (4 warps in n)
    const int bm   = blockIdx.y * 128;
    const int bn   = blockIdx.x * 128;

    const float* Ap = (MODE == 0) ? A : g_O;

    float acc[4][4][4];
#pragma unroll
    for (int i = 0; i < 4; i++)
#pragma unroll
        for (int j = 0; j < 4; j++)
#pragma unroll
            for (int r = 0; r < 4; r++) acc[i][j][r] = 0.f;

    const int a_r = tid >> 3, a_c = (tid & 7) * 4;    // A tile: 128x32
    const int b_r = tid >> 5, b_c = (tid & 31) * 4;   // B tile: 32x128

    for (int kt = 0; kt < DM / 32; kt++) {
#pragma unroll
        for (int i = 0; i < 4; i++) {
            int r = a_r + i * 32;
            float4 v = *(const float4*)(Ap + (size_t)(bm + r) * DM + kt * 32 + a_c);
            As[r * 36 + a_c + 0] = f2tf_f(v.x);
            As[r * 36 + a_c + 1] = f2tf_f(v.y);
            As[r * 36 + a_c + 2] = f2tf_f(v.z);
            As[r * 36 + a_c + 3] = f2tf_f(v.w);
        }
#pragma unroll
        for (int i = 0; i < 4; i++) {
            int r = b_r + i * 8;
            float4 v = *(const float4*)(W + (size_t)(kt * 32 + r) * DM + bn + b_c);
            Bs[r * 136 + b_c + 0] = f2tf_f(v.x);
            Bs[r * 136 + b_c + 1] = f2tf_f(v.y);
            Bs[r * 136 + b_c + 2] = f2tf_f(v.z);
            Bs[r * 136 + b_c + 3] = f2tf_f(v.w);
        }
        __syncthreads();

#pragma unroll
        for (int ks = 0; ks < 4; ks++) {
            uint32_t af[4][4];
#pragma unroll
            for (int mt = 0; mt < 4; mt++) {
                int r0 = wm + mt * 16 + gid;
                af[mt][0] = __float_as_uint(As[r0 * 36 + ks * 8 + tig]);
                af[mt][1] = __float_as_uint(As[(r0 + 8) * 36 + ks * 8 + tig]);
                af[mt][2] = __float_as_uint(As[r0 * 36 + ks * 8 + tig + 4]);
                af[mt][3] = __float_as_uint(As[(r0 + 8) * 36 + ks * 8 + tig + 4]);
            }
            uint32_t bf[4][2];
#pragma unroll
            for (int nt = 0; nt < 4; nt++) {
                int cc = wn + nt * 8 + gid;
                bf[nt][0] = __float_as_uint(Bs[(ks * 8 + tig) * 136 + cc]);
                bf[nt][1] = __float_as_uint(Bs[(ks * 8 + tig + 4) * 136 + cc]);
            }
#pragma unroll
            for (int mt = 0; mt < 4; mt++)
#pragma unroll
                for (int nt = 0; nt < 4; nt++)
                    mma8(acc[mt][nt], af[mt][0], af[mt][1], af[mt][2], af[mt][3],
                         bf[nt][0], bf[nt][1]);
        }
        __syncthreads();
    }

    // -------- epilogue --------
    float* C = Cout;
    if (MODE == 0) C = (which == 0) ? g_Q : (which == 1) ? g_K : g_V;

#pragma unroll
    for (int mt = 0; mt < 4; mt++) {
#pragma unroll
        for (int nt = 0; nt < 4; nt++) {
            int row = bm + wm + mt * 16 + gid;
            int col = bn + wn + nt * 8 + 2 * tig;
            if (MODE == 0) {
                // scatter to [B,H,N,64]
                int b = row >> 11, n = row & 2047;
                int h = col >> 6, d = col & 63;
                float2* p0 = (float2*)(C + ((((size_t)b * NH + h) * SEQ + n) * DH + d));
                *p0 = make_float2(acc[mt][nt][0], acc[mt][nt][1]);
                float2* p1 = (float2*)(C + ((((size_t)b * NH + h) * SEQ + (n + 8)) * DH + d));
                *p1 = make_float2(acc[mt][nt][2], acc[mt][nt][3]);
            } else {
                float2 bv = *(const float2*)(bias + col);
                *(float2*)(C + (size_t)row * DM + col) =
                    make_float2(acc[mt][nt][0] + bv.x, acc[mt][nt][1] + bv.y);
                *(float2*)(C + (size_t)(row + 8) * DM + col) =
                    make_float2(acc[mt][nt][2] + bv.x, acc[mt][nt][3] + bv.y);
            }
        }
    }
}

// ---------------- flash attention (TF32 mma, online softmax) ----------------
// grid: (SEQ/128, B*NH); block: 256 threads = 8 warps x 16 query rows
__global__ void __launch_bounds__(256) flash_attn() {
    __shared__ float Ks[64 * 68];   // stride 68: S b-frag banks 4*gid+tig
    __shared__ float Vs[64 * 72];   // stride 72: PV b-frag banks 8*tig+gid

    const int tid  = threadIdx.x;
    const int warp = tid >> 5, lane = tid & 31;
    const int gid  = lane >> 2, tig = lane & 3;
    const int qt = blockIdx.x, bh = blockIdx.y;

    const float* Qb = g_Q + (size_t)bh * SEQ * DH;
    const float* Kb = g_K + (size_t)bh * SEQ * DH;
    const float* Vb = g_V + (size_t)bh * SEQ * DH;

    const int   qr0 = qt * 128 + warp * 16;
    const float QS  = 0.125f * 1.4426950408889634f;  // scale * log2(e)

    // Q fragments: loaded once, pre-scaled + tf32-rounded
    uint32_t qf[8][4];
#pragma unroll
    for (int ks = 0; ks < 8; ks++) {
        int c = ks * 8 + tig;
        qf[ks][0] = f2tf(Qb[(size_t)(qr0 + gid) * DH + c] * QS);
        qf[ks][1] = f2tf(Qb[(size_t)(qr0 + gid + 8) * DH + c] * QS);
        qf[ks][2] = f2tf(Qb[(size_t)(qr0 + gid) * DH + c + 4] * QS);
        qf[ks][3] = f2tf(Qb[(size_t)(qr0 + gid + 8) * DH + c + 4] * QS);
    }

    float o[8][4];
#pragma unroll
    for (int nt = 0; nt < 8; nt++)
#pragma unroll
        for (int r = 0; r < 4; r++) o[nt][r] = 0.f;
    float m0 = -1e30f, m1 = -1e30f, l0 = 0.f, l1 = 0.f;

    const int tr = tid >> 4, tc = (tid & 15) * 4;   // K/V tile loading: 64 rows x 16 float4

    for (int kt = 0; kt < SEQ / 64; kt++) {
        __syncthreads();  // previous tile's smem reads done
#pragma unroll
        for (int i = 0; i < 4; i++) {
            int r = tr + i * 16;
            float4 kv = *(const float4*)(Kb + (size_t)(kt * 64 + r) * DH + tc);
            Ks[r * 68 + tc + 0] = f2tf_f(kv.x);
            Ks[r * 68 + tc + 1] = f2tf_f(kv.y);
            Ks[r * 68 + tc + 2] = f2tf_f(kv.z);
            Ks[r * 68 + tc + 3] = f2tf_f(kv.w);
            float4 vv = *(const float4*)(Vb + (size_t)(kt * 64 + r) * DH + tc);
            Vs[r * 72 + tc + 0] = f2tf_f(vv.x);
            Vs[r * 72 + tc + 1] = f2tf_f(vv.y);
            Vs[r * 72 + tc + 2] = f2tf_f(vv.z);
            Vs[r * 72 + tc + 3] = f2tf_f(vv.w);
        }
        __syncthreads();

        // ---- S = (Q*scale*log2e) K^T : [16 x 64] per warp ----
        float s[8][4];
#pragma unroll
        for (int nt = 0; nt < 8; nt++)
#pragma unroll
            for (int r = 0; r < 4; r++) s[nt][r] = 0.f;

#pragma unroll
        for (int ks = 0; ks < 8; ks++) {
#pragma unroll
            for (int nt = 0; nt < 8; nt++) {
                uint32_t b0 = __float_as_uint(Ks[(nt * 8 + gid) * 68 + ks * 8 + tig]);
                uint32_t b1 = __float_as_uint(Ks[(nt * 8 + gid) * 68 + ks * 8 + tig + 4]);
                mma8(s[nt], qf[ks][0], qf[ks][1], qf[ks][2], qf[ks][3], b0, b1);
            }
        }

        // ---- online softmax (exp2 domain) ----
        float tm0 = -1e30f, tm1 = -1e30f;
#pragma unroll
        for (int nt = 0; nt < 8; nt++) {
            tm0 = fmaxf(tm0, fmaxf(s[nt][0], s[nt][1]));
            tm1 = fmaxf(tm1, fmaxf(s[nt][2], s[nt][3]));
        }
        tm0 = fmaxf(tm0, __shfl_xor_sync(0xffffffffu, tm0, 1));
        tm0 = fmaxf(tm0, __shfl_xor_sync(0xffffffffu, tm0, 2));
        tm1 = fmaxf(tm1, __shfl_xor_sync(0xffffffffu, tm1, 1));
        tm1 = fmaxf(tm1, __shfl_xor_sync(0xffffffffu, tm1, 2));

        float mn0 = fmaxf(m0, tm0), mn1 = fmaxf(m1, tm1);
        float al0 = exp2f(m0 - mn0), al1 = exp2f(m1 - mn1);
        m0 = mn0; m1 = mn1;

        float rs0 = 0.f, rs1 = 0.f;
#pragma unroll
        for (int nt = 0; nt < 8; nt++) {
            float p0 = exp2f(s[nt][0] - m0);
            float p1 = exp2f(s[nt][1] - m0);
            float p2 = exp2f(s[nt][2] - m1);
            float p3 = exp2f(s[nt][3] - m1);
            rs0 += p0 + p1;
            rs1 += p2 + p3;
            s[nt][0] = f2tf_f(p0);
            s[nt][1] = f2tf_f(p1);
            s[nt][2] = f2tf_f(p2);
            s[nt][3] = f2tf_f(p3);
        }
        rs0 += __shfl_xor_sync(0xffffffffu, rs0, 1);
        rs0 += __shfl_xor_sync(0xffffffffu, rs0, 2);
        rs1 += __shfl_xor_sync(0xffffffffu, rs1, 1);
        rs1 += __shfl_xor_sync(0xffffffffu, rs1, 2);
        l0 = l0 * al0 + rs0;
        l1 = l1 * al1 + rs1;

#pragma unroll
        for (int nt = 0; nt < 8; nt++) {
            o[nt][0] *= al0; o[nt][1] *= al0;
            o[nt][2] *= al1; o[nt][3] *= al1;
        }

        // ---- O += P V : shuffle-reshape P (c-frag) into A-frag layout ----
#pragma unroll
        for (int ks = 0; ks < 8; ks++) {
            int srcA = (lane & ~3) | (tig >> 1);
            int srcB = srcA + 2;
            float w00 = __shfl_sync(0xffffffffu, s[ks][0], srcA);
            float w01 = __shfl_sync(0xffffffffu, s[ks][1], srcA);
            float w02 = __shfl_sync(0xffffffffu, s[ks][0], srcB);
            float w03 = __shfl_sync(0xffffffffu, s[ks][1], srcB);
            float w10 = __shfl_sync(0xffffffffu, s[ks][2], srcA);
            float w11 = __shfl_sync(0xffffffffu, s[ks][3], srcA);
            float w12 = __shfl_sync(0xffffffffu, s[ks][2], srcB);
            float w13 = __shfl_sync(0xffffffffu, s[ks][3], srcB);
            bool odd = (tig & 1);
            uint32_t pa0 = __float_as_uint(odd ? w01 : w00);
            uint32_t pa2 = __float_as_uint(odd ? w03 : w02);
            uint32_t pa1 = __float_as_uint(odd ? w11 : w10);
            uint32_t pa3 = __float_as_uint(odd ? w13 : w12);
#pragma unroll
            for (int nt = 0; nt < 8; nt++) {
                uint32_t b0 = __float_as_uint(Vs[(ks * 8 + tig) * 72 + nt * 8 + gid]);
                uint32_t b1 = __float_as_uint(Vs[(ks * 8 + tig + 4) * 72 + nt * 8 + gid]);
                mma8(o[nt], pa0, pa1, pa2, pa3, b0, b1);
            }
        }
    }

    // ---- normalize + write O to [B, N, H*64] ----
    float i0 = 1.f / l0, i1 = 1.f / l1;
    int b = bh >> 4, h = bh & 15;
    int row0 = qr0 + gid;
#pragma unroll
    for (int nt = 0; nt < 8; nt++) {
        int col = h * 64 + nt * 8 + 2 * tig;
        *(float2*)(g_O + (size_t)(b * SEQ + row0) * DM + col) =
            make_float2(o[nt][0] * i0, o[nt][1] * i0);
        *(float2*)(g_O + (size_t)(b * SEQ + row0 + 8) * DM + col) =
            make_float2(o[nt][2] * i1, o[nt][3] * i1);
    }
}

// ---------------- launch ----------------
extern "C" void kernel_launch(void* const* d_in, const int* in_sizes, int n_in,
                              void* d_out, int out_size) {
    const float* q  = (const float*)d_in[0];
    const float* k  = (const float*)d_in[1];
    const float* v  = (const float*)d_in[2];
    const float* Wq = (const float*)d_in[3];
    const float* Wk = (const float*)d_in[4];
    const float* Wv = (const float*)d_in[5];
    const float* Wo = (const float*)d_in[6];
    const float* bo = (const float*)d_in[7];
    float* out = (float*)d_out;

    dim3 g(DM / 128, MROWS / 128);  // (8, 32)
    gemm_tf32<0><<<g, 256>>>(q, Wq, nullptr, nullptr, 0);
    gemm_tf32<0><<<g, 256>>>(k, Wk, nullptr, nullptr, 1);
    gemm_tf32<0><<<g, 256>>>(v, Wv, nullptr, nullptr, 2);
    flash_attn<<<dim3(SEQ / 128, BATCH * NH), 256>>>();
    gemm_tf32<1><<<g, 256>>>(nullptr, Wo, bo, out, 3);
}